// round 2
// baseline (speedup 1.0000x reference)
#include <cuda_runtime.h>
#include <cuda_bf16.h>

#define NP 110000
#define NT 20000
#define NG 10000
#define NTOT (NP + NT + NG)   // 140000
#define EE 500000
#define DD 64

// ---- scratch (static device memory; no allocations allowed) ----
__device__ int   g_deg[NTOT];              // in-degree per global node
__device__ int   g_off[NTOT + 1];          // CSR row offsets (global)
__device__ int   g_cur[NTOT];              // scatter cursors
__device__ int   g_adj[3 * EE];            // CSR adjacency: local src index
__device__ float g_dinv[NTOT];             // rsqrt(in-degree)
__device__ __align__(16) float g_x1[(size_t)NTOT * DD];  // layer-1 output
__device__ __align__(16) float g_x2[(size_t)NTOT * DD];  // final table p (after conv2 epilogue)

// ---------------------------------------------------------------
__global__ void zero_deg_kernel() {
    int i = blockIdx.x * blockDim.x + threadIdx.x;
    if (i < NTOT) g_deg[i] = 0;
}

// in-degree histogram for all three graphs
__global__ void degree_kernel(const int* __restrict__ up,
                              const int* __restrict__ ut,
                              const int* __restrict__ ug) {
    int i = blockIdx.x * blockDim.x + threadIdx.x;
    if (i < EE) {
        atomicAdd(&g_deg[up[EE + i]], 1);
    } else if (i < 2 * EE) {
        atomicAdd(&g_deg[NP + ut[EE + (i - EE)]], 1);
    } else if (i < 3 * EE) {
        atomicAdd(&g_deg[NP + NT + ug[EE + (i - 2 * EE)]], 1);
    }
}

// single-block exclusive scan of g_deg -> g_off / g_cur, plus dinv
__global__ void scan_kernel() {
    __shared__ int part[1024];
    const int t = threadIdx.x;
    const int CH = (NTOT + 1023) / 1024;          // 137
    int beg = t * CH;
    int end = min(beg + CH, NTOT);

    int s = 0;
    for (int i = beg; i < end; i++) s += g_deg[i];
    part[t] = s;
    __syncthreads();
    // Hillis-Steele inclusive scan
    for (int o = 1; o < 1024; o <<= 1) {
        int v = (t >= o) ? part[t - o] : 0;
        __syncthreads();
        part[t] += v;
        __syncthreads();
    }
    int run = (t == 0) ? 0 : part[t - 1];
    for (int i = beg; i < end; i++) {
        g_off[i] = run;
        g_cur[i] = run;
        run += g_deg[i];
        int d = g_deg[i];
        g_dinv[i] = (d > 0) ? rsqrtf((float)d) : 0.f;
    }
    if (t == 1023) g_off[NTOT] = run;
}

// scatter edges into CSR (order within a row is irrelevant — we only sum)
__global__ void build_adj_kernel(const int* __restrict__ up,
                                 const int* __restrict__ ut,
                                 const int* __restrict__ ug) {
    int i = blockIdx.x * blockDim.x + threadIdx.x;
    if (i < EE) {
        int s = up[i], d = up[EE + i];
        int pos = atomicAdd(&g_cur[d], 1);
        g_adj[pos] = s;
    } else if (i < 2 * EE) {
        int e = i - EE;
        int s = ut[e], d = ut[EE + e];
        int pos = atomicAdd(&g_cur[NP + d], 1);
        g_adj[pos] = s;
    } else if (i < 3 * EE) {
        int e = i - 2 * EE;
        int s = ug[e], d = ug[EE + e];
        int pos = atomicAdd(&g_cur[NP + NT + d], 1);
        g_adj[pos] = s;
    }
}

// warp-per-node segment sum: out[n] = dinv[n] * sum_{s in adj(n)} dinv[s] * tab[s]
// lane owns dims {2*lane, 2*lane+1}; 4-way unroll for MLP.
// Layer 1: tab = external embedding table of the node's graph -> writes g_x1.
__global__ void __launch_bounds__(256)
conv1_kernel(const float* __restrict__ e0, const float* __restrict__ e1,
             const float* __restrict__ e2) {
    int n = (blockIdx.x * blockDim.x + threadIdx.x) >> 5;
    if (n >= NTOT) return;
    int lane = threadIdx.x & 31;
    int o = lane << 1;

    const float* tab;
    int base;
    if (n < NP)            { tab = e0; base = 0; }
    else if (n < NP + NT)  { tab = e1; base = NP; }
    else                   { tab = e2; base = NP + NT; }

    int beg = g_off[n], end = g_off[n + 1];
    float ax = 0.f, ay = 0.f;
    int k = beg;
    for (; k + 4 <= end; k += 4) {
        int s0 = g_adj[k], s1 = g_adj[k + 1], s2 = g_adj[k + 2], s3 = g_adj[k + 3];
        float w0 = g_dinv[base + s0], w1 = g_dinv[base + s1];
        float w2 = g_dinv[base + s2], w3 = g_dinv[base + s3];
        float2 v0 = *reinterpret_cast<const float2*>(tab + (size_t)s0 * DD + o);
        float2 v1 = *reinterpret_cast<const float2*>(tab + (size_t)s1 * DD + o);
        float2 v2 = *reinterpret_cast<const float2*>(tab + (size_t)s2 * DD + o);
        float2 v3 = *reinterpret_cast<const float2*>(tab + (size_t)s3 * DD + o);
        ax += w0 * v0.x + w1 * v1.x + w2 * v2.x + w3 * v3.x;
        ay += w0 * v0.y + w1 * v1.y + w2 * v2.y + w3 * v3.y;
    }
    for (; k < end; k++) {
        int s = g_adj[k];
        float w = g_dinv[base + s];
        float2 v = *reinterpret_cast<const float2*>(tab + (size_t)s * DD + o);
        ax += w * v.x;
        ay += w * v.y;
    }
    float wd = g_dinv[n];
    *reinterpret_cast<float2*>(g_x1 + (size_t)n * DD + o) =
        make_float2(ax * wd, ay * wd);
}

// Layer 2 + fused finalize: x2 = conv(g_x1); p = (emb + x1 + x2)/3 -> g_x2
__global__ void __launch_bounds__(256)
conv2_kernel(const float* __restrict__ e0, const float* __restrict__ e1,
             const float* __restrict__ e2) {
    int n = (blockIdx.x * blockDim.x + threadIdx.x) >> 5;
    if (n >= NTOT) return;
    int lane = threadIdx.x & 31;
    int o = lane << 1;

    const float* emb;
    int base;
    if (n < NP)            { emb = e0; base = 0; }
    else if (n < NP + NT)  { emb = e1; base = NP; }
    else                   { emb = e2; base = NP + NT; }
    const float* tab = g_x1 + (size_t)base * DD;

    int beg = g_off[n], end = g_off[n + 1];
    float ax = 0.f, ay = 0.f;
    int k = beg;
    for (; k + 4 <= end; k += 4) {
        int s0 = g_adj[k], s1 = g_adj[k + 1], s2 = g_adj[k + 2], s3 = g_adj[k + 3];
        float w0 = g_dinv[base + s0], w1 = g_dinv[base + s1];
        float w2 = g_dinv[base + s2], w3 = g_dinv[base + s3];
        float2 v0 = *reinterpret_cast<const float2*>(tab + (size_t)s0 * DD + o);
        float2 v1 = *reinterpret_cast<const float2*>(tab + (size_t)s1 * DD + o);
        float2 v2 = *reinterpret_cast<const float2*>(tab + (size_t)s2 * DD + o);
        float2 v3 = *reinterpret_cast<const float2*>(tab + (size_t)s3 * DD + o);
        ax += w0 * v0.x + w1 * v1.x + w2 * v2.x + w3 * v3.x;
        ay += w0 * v0.y + w1 * v1.y + w2 * v2.y + w3 * v3.y;
    }
    for (; k < end; k++) {
        int s = g_adj[k];
        float w = g_dinv[base + s];
        float2 v = *reinterpret_cast<const float2*>(tab + (size_t)s * DD + o);
        ax += w * v.x;
        ay += w * v.y;
    }
    float wd = g_dinv[n];
    float x2x = ax * wd, x2y = ay * wd;

    size_t idx = (size_t)n * DD + o;
    float2 ev  = *reinterpret_cast<const float2*>(emb + (size_t)(n - base) * DD + o);
    float2 x1v = *reinterpret_cast<const float2*>(g_x1 + idx);
    const float k3 = 1.f / 3.f;
    *reinterpret_cast<float2*>(g_x2 + idx) =
        make_float2((ev.x + x1v.x + x2x) * k3, (ev.y + x1v.y + x2y) * k3);
}

// final fused per-edge kernel: feature linears + 6 gathers (from g_x2) + dot
__global__ void __launch_bounds__(256)
final_kernel(const int* __restrict__ up, const int* __restrict__ ut,
             const int* __restrict__ ug,
             const float* __restrict__ sfeat, const float* __restrict__ dfeat,
             const float* __restrict__ Ws, const float* __restrict__ bs,
             const float* __restrict__ Wd, const float* __restrict__ bd,
             float* __restrict__ out) {
    __shared__ float sWs[16 * 64];
    __shared__ float sWd[16 * 64];
    __shared__ float sbs[64];
    __shared__ float sbd[64];
    int t = threadIdx.x;
    for (int i = t; i < 1024; i += blockDim.x) { sWs[i] = Ws[i]; sWd[i] = Wd[i]; }
    if (t < 64) { sbs[t] = bs[t]; sbd[t] = bd[t]; }
    __syncthreads();

    int e = (blockIdx.x * blockDim.x + t) >> 5;
    if (e >= EE) return;
    int lane = t & 31;
    int d2 = lane << 1;

    float fsv = sfeat[e * 16 + (lane & 15)];
    float fdv = dfeat[e * 16 + (lane & 15)];
    float fs0 = sbs[d2], fs1 = sbs[d2 + 1];
    float fd0 = sbd[d2], fd1 = sbd[d2 + 1];
#pragma unroll
    for (int k = 0; k < 16; k++) {
        float a = __shfl_sync(0xffffffffu, fsv, k);
        float b = __shfl_sync(0xffffffffu, fdv, k);
        float2 ws = *reinterpret_cast<const float2*>(sWs + k * 64 + d2);
        float2 wd = *reinterpret_cast<const float2*>(sWd + k * 64 + d2);
        fs0 = fmaf(a, ws.x, fs0); fs1 = fmaf(a, ws.y, fs1);
        fd0 = fmaf(b, wd.x, fd0); fd1 = fmaf(b, wd.y, fd1);
    }

    int s0 = up[e], dn0 = up[EE + e];
    int s1 = ut[e], dn1 = ut[EE + e];
    int s2 = ug[e], dn2 = ug[EE + e];
    const float* P = g_x2;
    const float* T = g_x2 + (size_t)NP * DD;
    const float* G = g_x2 + (size_t)(NP + NT) * DD;

    float2 ps = *reinterpret_cast<const float2*>(P + (size_t)s0 * DD + d2);
    float2 ts = *reinterpret_cast<const float2*>(T + (size_t)s1 * DD + d2);
    float2 gs = *reinterpret_cast<const float2*>(G + (size_t)s2 * DD + d2);
    float2 pd = *reinterpret_cast<const float2*>(P + (size_t)dn0 * DD + d2);
    float2 td = *reinterpret_cast<const float2*>(T + (size_t)dn1 * DD + d2);
    float2 gd = *reinterpret_cast<const float2*>(G + (size_t)dn2 * DD + d2);

    const float k3 = 1.f / 3.f;
    float os0 = (ps.x + ts.x + gs.x) * k3 + fs0;
    float os1 = (ps.y + ts.y + gs.y) * k3 + fs1;
    float od0 = (pd.x + td.x + gd.x) * k3 + fd0;
    float od1 = (pd.y + td.y + gd.y) * k3 + fd1;

    float partial = os0 * od0 + os1 * od1;
#pragma unroll
    for (int o = 16; o; o >>= 1)
        partial += __shfl_xor_sync(0xffffffffu, partial, o);
    if (lane == 0) out[e] = partial;
}

// ---------------------------------------------------------------
extern "C" void kernel_launch(void* const* d_in, const int* in_sizes, int n_in,
                              void* d_out, int out_size) {
    const int*   up     = (const int*)d_in[0];
    const int*   ut     = (const int*)d_in[1];
    const int*   ug     = (const int*)d_in[2];
    const float* sfeat  = (const float*)d_in[3];
    const float* dfeat  = (const float*)d_in[4];
    const float* up_emb = (const float*)d_in[5];
    const float* ut_emb = (const float*)d_in[6];
    const float* ug_emb = (const float*)d_in[7];
    const float* W_src  = (const float*)d_in[8];
    const float* b_src  = (const float*)d_in[9];
    const float* W_dst  = (const float*)d_in[10];
    const float* b_dst  = (const float*)d_in[11];
    float* out = (float*)d_out;

    zero_deg_kernel<<<(NTOT + 255) / 256, 256>>>();
    degree_kernel<<<(3 * EE + 255) / 256, 256>>>(up, ut, ug);
    scan_kernel<<<1, 1024>>>();
    build_adj_kernel<<<(3 * EE + 255) / 256, 256>>>(up, ut, ug);

    const int convGrid = (NTOT * 32 + 255) / 256;
    conv1_kernel<<<convGrid, 256>>>(up_emb, ut_emb, ug_emb);
    conv2_kernel<<<convGrid, 256>>>(up_emb, ut_emb, ug_emb);

    final_kernel<<<(EE * 32 + 255) / 256, 256>>>(up, ut, ug, sfeat, dfeat,
                                                 W_src, b_src, W_dst, b_dst, out);
}

// round 3
// speedup vs baseline: 1.7313x; 1.7313x over previous
#include <cuda_runtime.h>
#include <cuda_bf16.h>

#define NP 110000
#define NT 20000
#define NG 10000
#define NTOT (NP + NT + NG)   // 140000
#define EE 500000
#define DD 64

#define SCAN_CHUNK 1024
#define NBLK ((NTOT + SCAN_CHUNK - 1) / SCAN_CHUNK)   // 137

// ---- scratch (static device memory; no allocations allowed) ----
__device__ int   g_deg[NTOT];              // in-degree per global node
__device__ int   g_off[NTOT + 1];          // CSR row offsets (global)
__device__ int   g_cur[NTOT];              // scatter cursors
__device__ int   g_bsum[NBLK];             // per-block sums for scan
__device__ int   g_boff[NBLK];             // exclusive block offsets
__device__ int   g_adj[3 * EE];            // CSR adjacency: local src index
__device__ float g_dinv[NTOT];             // rsqrt(in-degree)
__device__ __align__(16) float g_x1[(size_t)NTOT * DD];  // layer-1 output
__device__ __align__(16) float g_x2[(size_t)NTOT * DD];  // final table p

// ---------------------------------------------------------------
// in-degree histogram for all three graphs
__global__ void degree_kernel(const int* __restrict__ up,
                              const int* __restrict__ ut,
                              const int* __restrict__ ug) {
    int i = blockIdx.x * blockDim.x + threadIdx.x;
    if (i < EE) {
        atomicAdd(&g_deg[up[EE + i]], 1);
    } else if (i < 2 * EE) {
        atomicAdd(&g_deg[NP + ut[EE + (i - EE)]], 1);
    } else if (i < 3 * EE) {
        atomicAdd(&g_deg[NP + NT + ug[EE + (i - 2 * EE)]], 1);
    }
}

// phase 1: per-block exclusive prescan of g_deg into g_off, block sums to g_bsum
__global__ void scan1_kernel() {
    __shared__ int wsum[8];
    int blk = blockIdx.x;
    int t = threadIdx.x;          // 256
    int lane = t & 31, wid = t >> 5;
    int base = blk * SCAN_CHUNK + t * 4;

    int v0 = 0, v1 = 0, v2 = 0, v3 = 0;
    if (base + 3 < NTOT) {
        v0 = g_deg[base]; v1 = g_deg[base + 1];
        v2 = g_deg[base + 2]; v3 = g_deg[base + 3];
    } else {
        if (base     < NTOT) v0 = g_deg[base];
        if (base + 1 < NTOT) v1 = g_deg[base + 1];
        if (base + 2 < NTOT) v2 = g_deg[base + 2];
        if (base + 3 < NTOT) v3 = g_deg[base + 3];
    }
    int s = v0 + v1 + v2 + v3;
    // warp inclusive scan of s
    int inc = s;
#pragma unroll
    for (int o = 1; o < 32; o <<= 1) {
        int n = __shfl_up_sync(0xffffffffu, inc, o);
        if (lane >= o) inc += n;
    }
    if (lane == 31) wsum[wid] = inc;
    __syncthreads();
    if (t == 0) {
        int run = 0;
#pragma unroll
        for (int w = 0; w < 8; w++) { int x = wsum[w]; wsum[w] = run; run += x; }
        g_bsum[blk] = run;
    }
    __syncthreads();
    int ex = inc - s + wsum[wid];     // exclusive prefix for this thread's chunk
    if (base     < NTOT) g_off[base]     = ex;
    if (base + 1 < NTOT) g_off[base + 1] = ex + v0;
    if (base + 2 < NTOT) g_off[base + 2] = ex + v0 + v1;
    if (base + 3 < NTOT) g_off[base + 3] = ex + v0 + v1 + v2;
}

// phase 2: scan the 137 block sums (single small block)
__global__ void scan2_kernel() {
    __shared__ int sh[256];
    int t = threadIdx.x;
    int v = (t < NBLK) ? g_bsum[t] : 0;
    sh[t] = v;
    __syncthreads();
    for (int o = 1; o < 256; o <<= 1) {
        int n = (t >= o) ? sh[t - o] : 0;
        __syncthreads();
        sh[t] += n;
        __syncthreads();
    }
    if (t < NBLK) g_boff[t] = sh[t] - v;   // exclusive
    if (t == 255) g_off[NTOT] = sh[255];   // grand total (3*EE)
}

// phase 3: add block offsets, init cursors + dinv
__global__ void scan3_kernel() {
    int i = blockIdx.x * blockDim.x + threadIdx.x;
    if (i >= NTOT) return;
    int off = g_off[i] + g_boff[i >> 10];
    g_off[i] = off;
    g_cur[i] = off;
    int d = g_deg[i];
    g_dinv[i] = (d > 0) ? rsqrtf((float)d) : 0.f;
}

// scatter edges into CSR (order within a row irrelevant — we only sum)
__global__ void build_adj_kernel(const int* __restrict__ up,
                                 const int* __restrict__ ut,
                                 const int* __restrict__ ug) {
    int i = blockIdx.x * blockDim.x + threadIdx.x;
    if (i < EE) {
        int s = up[i], d = up[EE + i];
        int pos = atomicAdd(&g_cur[d], 1);
        g_adj[pos] = s;
    } else if (i < 2 * EE) {
        int e = i - EE;
        int s = ut[e], d = ut[EE + e];
        int pos = atomicAdd(&g_cur[NP + d], 1);
        g_adj[pos] = s;
    } else if (i < 3 * EE) {
        int e = i - 2 * EE;
        int s = ug[e], d = ug[EE + e];
        int pos = atomicAdd(&g_cur[NP + NT + d], 1);
        g_adj[pos] = s;
    }
}

// warp-per-node segment sum: out[n] = dinv[n] * sum_{s in adj(n)} dinv[s] * tab[s]
__global__ void __launch_bounds__(256)
conv1_kernel(const float* __restrict__ e0, const float* __restrict__ e1,
             const float* __restrict__ e2) {
    int n = (blockIdx.x * blockDim.x + threadIdx.x) >> 5;
    if (n >= NTOT) return;
    int lane = threadIdx.x & 31;
    int o = lane << 1;

    const float* tab;
    int base;
    if (n < NP)            { tab = e0; base = 0; }
    else if (n < NP + NT)  { tab = e1; base = NP; }
    else                   { tab = e2; base = NP + NT; }

    int beg = g_off[n], end = g_off[n + 1];
    float ax = 0.f, ay = 0.f;
    int k = beg;
    for (; k + 4 <= end; k += 4) {
        int s0 = g_adj[k], s1 = g_adj[k + 1], s2 = g_adj[k + 2], s3 = g_adj[k + 3];
        float w0 = g_dinv[base + s0], w1 = g_dinv[base + s1];
        float w2 = g_dinv[base + s2], w3 = g_dinv[base + s3];
        float2 v0 = *reinterpret_cast<const float2*>(tab + (size_t)s0 * DD + o);
        float2 v1 = *reinterpret_cast<const float2*>(tab + (size_t)s1 * DD + o);
        float2 v2 = *reinterpret_cast<const float2*>(tab + (size_t)s2 * DD + o);
        float2 v3 = *reinterpret_cast<const float2*>(tab + (size_t)s3 * DD + o);
        ax += w0 * v0.x + w1 * v1.x + w2 * v2.x + w3 * v3.x;
        ay += w0 * v0.y + w1 * v1.y + w2 * v2.y + w3 * v3.y;
    }
    for (; k < end; k++) {
        int s = g_adj[k];
        float w = g_dinv[base + s];
        float2 v = *reinterpret_cast<const float2*>(tab + (size_t)s * DD + o);
        ax += w * v.x;
        ay += w * v.y;
    }
    float wd = g_dinv[n];
    *reinterpret_cast<float2*>(g_x1 + (size_t)n * DD + o) =
        make_float2(ax * wd, ay * wd);
}

// Layer 2 + fused finalize: x2 = conv(g_x1); p = (emb + x1 + x2)/3 -> g_x2
__global__ void __launch_bounds__(256)
conv2_kernel(const float* __restrict__ e0, const float* __restrict__ e1,
             const float* __restrict__ e2) {
    int n = (blockIdx.x * blockDim.x + threadIdx.x) >> 5;
    if (n >= NTOT) return;
    int lane = threadIdx.x & 31;
    int o = lane << 1;

    const float* emb;
    int base;
    if (n < NP)            { emb = e0; base = 0; }
    else if (n < NP + NT)  { emb = e1; base = NP; }
    else                   { emb = e2; base = NP + NT; }
    const float* tab = g_x1 + (size_t)base * DD;

    int beg = g_off[n], end = g_off[n + 1];
    float ax = 0.f, ay = 0.f;
    int k = beg;
    for (; k + 4 <= end; k += 4) {
        int s0 = g_adj[k], s1 = g_adj[k + 1], s2 = g_adj[k + 2], s3 = g_adj[k + 3];
        float w0 = g_dinv[base + s0], w1 = g_dinv[base + s1];
        float w2 = g_dinv[base + s2], w3 = g_dinv[base + s3];
        float2 v0 = *reinterpret_cast<const float2*>(tab + (size_t)s0 * DD + o);
        float2 v1 = *reinterpret_cast<const float2*>(tab + (size_t)s1 * DD + o);
        float2 v2 = *reinterpret_cast<const float2*>(tab + (size_t)s2 * DD + o);
        float2 v3 = *reinterpret_cast<const float2*>(tab + (size_t)s3 * DD + o);
        ax += w0 * v0.x + w1 * v1.x + w2 * v2.x + w3 * v3.x;
        ay += w0 * v0.y + w1 * v1.y + w2 * v2.y + w3 * v3.y;
    }
    for (; k < end; k++) {
        int s = g_adj[k];
        float w = g_dinv[base + s];
        float2 v = *reinterpret_cast<const float2*>(tab + (size_t)s * DD + o);
        ax += w * v.x;
        ay += w * v.y;
    }
    float wd = g_dinv[n];
    float x2x = ax * wd, x2y = ay * wd;

    size_t idx = (size_t)n * DD + o;
    float2 ev  = *reinterpret_cast<const float2*>(emb + (size_t)(n - base) * DD + o);
    float2 x1v = *reinterpret_cast<const float2*>(g_x1 + idx);
    const float k3 = 1.f / 3.f;
    *reinterpret_cast<float2*>(g_x2 + idx) =
        make_float2((ev.x + x1v.x + x2x) * k3, (ev.y + x1v.y + x2y) * k3);
}

// final fused per-edge kernel: feature linears + 6 gathers (from g_x2) + dot
__global__ void __launch_bounds__(256)
final_kernel(const int* __restrict__ up, const int* __restrict__ ut,
             const int* __restrict__ ug,
             const float* __restrict__ sfeat, const float* __restrict__ dfeat,
             const float* __restrict__ Ws, const float* __restrict__ bs,
             const float* __restrict__ Wd, const float* __restrict__ bd,
             float* __restrict__ out) {
    __shared__ float sWs[16 * 64];
    __shared__ float sWd[16 * 64];
    __shared__ float sbs[64];
    __shared__ float sbd[64];
    int t = threadIdx.x;
    for (int i = t; i < 1024; i += blockDim.x) { sWs[i] = Ws[i]; sWd[i] = Wd[i]; }
    if (t < 64) { sbs[t] = bs[t]; sbd[t] = bd[t]; }
    __syncthreads();

    int e = (blockIdx.x * blockDim.x + t) >> 5;
    if (e >= EE) return;
    int lane = t & 31;
    int d2 = lane << 1;

    float fsv = sfeat[e * 16 + (lane & 15)];
    float fdv = dfeat[e * 16 + (lane & 15)];
    float fs0 = sbs[d2], fs1 = sbs[d2 + 1];
    float fd0 = sbd[d2], fd1 = sbd[d2 + 1];
#pragma unroll
    for (int k = 0; k < 16; k++) {
        float a = __shfl_sync(0xffffffffu, fsv, k);
        float b = __shfl_sync(0xffffffffu, fdv, k);
        float2 ws = *reinterpret_cast<const float2*>(sWs + k * 64 + d2);
        float2 wd = *reinterpret_cast<const float2*>(sWd + k * 64 + d2);
        fs0 = fmaf(a, ws.x, fs0); fs1 = fmaf(a, ws.y, fs1);
        fd0 = fmaf(b, wd.x, fd0); fd1 = fmaf(b, wd.y, fd1);
    }

    int s0 = up[e], dn0 = up[EE + e];
    int s1 = ut[e], dn1 = ut[EE + e];
    int s2 = ug[e], dn2 = ug[EE + e];
    const float* P = g_x2;
    const float* T = g_x2 + (size_t)NP * DD;
    const float* G = g_x2 + (size_t)(NP + NT) * DD;

    float2 ps = *reinterpret_cast<const float2*>(P + (size_t)s0 * DD + d2);
    float2 ts = *reinterpret_cast<const float2*>(T + (size_t)s1 * DD + d2);
    float2 gs = *reinterpret_cast<const float2*>(G + (size_t)s2 * DD + d2);
    float2 pd = *reinterpret_cast<const float2*>(P + (size_t)dn0 * DD + d2);
    float2 td = *reinterpret_cast<const float2*>(T + (size_t)dn1 * DD + d2);
    float2 gd = *reinterpret_cast<const float2*>(G + (size_t)dn2 * DD + d2);

    const float k3 = 1.f / 3.f;
    float os0 = (ps.x + ts.x + gs.x) * k3 + fs0;
    float os1 = (ps.y + ts.y + gs.y) * k3 + fs1;
    float od0 = (pd.x + td.x + gd.x) * k3 + fd0;
    float od1 = (pd.y + td.y + gd.y) * k3 + fd1;

    float partial = os0 * od0 + os1 * od1;
#pragma unroll
    for (int o = 16; o; o >>= 1)
        partial += __shfl_xor_sync(0xffffffffu, partial, o);
    if (lane == 0) out[e] = partial;
}

// ---------------------------------------------------------------
extern "C" void kernel_launch(void* const* d_in, const int* in_sizes, int n_in,
                              void* d_out, int out_size) {
    const int*   up     = (const int*)d_in[0];
    const int*   ut     = (const int*)d_in[1];
    const int*   ug     = (const int*)d_in[2];
    const float* sfeat  = (const float*)d_in[3];
    const float* dfeat  = (const float*)d_in[4];
    const float* up_emb = (const float*)d_in[5];
    const float* ut_emb = (const float*)d_in[6];
    const float* ug_emb = (const float*)d_in[7];
    const float* W_src  = (const float*)d_in[8];
    const float* b_src  = (const float*)d_in[9];
    const float* W_dst  = (const float*)d_in[10];
    const float* b_dst  = (const float*)d_in[11];
    float* out = (float*)d_out;

    // zero the degree histogram (async memset is graph-capturable)
    void* degPtr = nullptr;
    cudaGetSymbolAddress(&degPtr, g_deg);
    cudaMemsetAsync(degPtr, 0, NTOT * sizeof(int));

    degree_kernel<<<(3 * EE + 255) / 256, 256>>>(up, ut, ug);
    scan1_kernel<<<NBLK, 256>>>();
    scan2_kernel<<<1, 256>>>();
    scan3_kernel<<<(NTOT + 255) / 256, 256>>>();
    build_adj_kernel<<<(3 * EE + 255) / 256, 256>>>(up, ut, ug);

    const int convGrid = (NTOT * 32 + 255) / 256;
    conv1_kernel<<<convGrid, 256>>>(up_emb, ut_emb, ug_emb);
    conv2_kernel<<<convGrid, 256>>>(up_emb, ut_emb, ug_emb);

    final_kernel<<<(EE * 32 + 255) / 256, 256>>>(up, ut, ug, sfeat, dfeat,
                                                 W_src, b_src, W_dst, b_dst, out);
}

// round 4
// speedup vs baseline: 1.7417x; 1.0060x over previous
#include <cuda_runtime.h>
#include <cuda_bf16.h>

#define NP 110000
#define NT 20000
#define NG 10000
#define NTOT (NP + NT + NG)   // 140000
#define EE 500000
#define DD 64

#define SCAN_CHUNK 1024
#define NBLK ((NTOT + SCAN_CHUNK - 1) / SCAN_CHUNK)   // 137

// ---- scratch (static device memory; no allocations allowed) ----
__device__ int   g_deg[NTOT];
__device__ int   g_off[NTOT + 1];
__device__ int   g_cur[NTOT];
__device__ int   g_bsum[NBLK];
__device__ int   g_boff[NBLK];
__device__ int   g_adj[3 * EE];
__device__ float g_dinv[NTOT];
__device__ __align__(16) float g_x1[(size_t)NTOT * DD];
__device__ __align__(16) float g_x2[(size_t)NTOT * DD];

// ---------------------------------------------------------------
// in-degree histogram, int4-vectorized (4 edges per thread)
__global__ void degree_kernel(const int* __restrict__ up,
                              const int* __restrict__ ut,
                              const int* __restrict__ ug) {
    const int Q = EE / 4;   // 125000
    int i = blockIdx.x * blockDim.x + threadIdx.x;
    if (i < Q) {
        int4 d = reinterpret_cast<const int4*>(up + EE)[i];
        atomicAdd(&g_deg[d.x], 1); atomicAdd(&g_deg[d.y], 1);
        atomicAdd(&g_deg[d.z], 1); atomicAdd(&g_deg[d.w], 1);
    } else if (i < 2 * Q) {
        int4 d = reinterpret_cast<const int4*>(ut + EE)[i - Q];
        atomicAdd(&g_deg[NP + d.x], 1); atomicAdd(&g_deg[NP + d.y], 1);
        atomicAdd(&g_deg[NP + d.z], 1); atomicAdd(&g_deg[NP + d.w], 1);
    } else if (i < 3 * Q) {
        int4 d = reinterpret_cast<const int4*>(ug + EE)[i - 2 * Q];
        atomicAdd(&g_deg[NP + NT + d.x], 1); atomicAdd(&g_deg[NP + NT + d.y], 1);
        atomicAdd(&g_deg[NP + NT + d.z], 1); atomicAdd(&g_deg[NP + NT + d.w], 1);
    }
}

// phase 1: per-block exclusive prescan of g_deg into g_off, block sums to g_bsum
__global__ void scan1_kernel() {
    __shared__ int wsum[8];
    int blk = blockIdx.x;
    int t = threadIdx.x;          // 256
    int lane = t & 31, wid = t >> 5;
    int base = blk * SCAN_CHUNK + t * 4;

    int v0 = 0, v1 = 0, v2 = 0, v3 = 0;
    if (base + 3 < NTOT) {
        v0 = g_deg[base]; v1 = g_deg[base + 1];
        v2 = g_deg[base + 2]; v3 = g_deg[base + 3];
    } else {
        if (base     < NTOT) v0 = g_deg[base];
        if (base + 1 < NTOT) v1 = g_deg[base + 1];
        if (base + 2 < NTOT) v2 = g_deg[base + 2];
        if (base + 3 < NTOT) v3 = g_deg[base + 3];
    }
    int s = v0 + v1 + v2 + v3;
    int inc = s;
#pragma unroll
    for (int o = 1; o < 32; o <<= 1) {
        int n = __shfl_up_sync(0xffffffffu, inc, o);
        if (lane >= o) inc += n;
    }
    if (lane == 31) wsum[wid] = inc;
    __syncthreads();
    if (t == 0) {
        int run = 0;
#pragma unroll
        for (int w = 0; w < 8; w++) { int x = wsum[w]; wsum[w] = run; run += x; }
        g_bsum[blk] = run;
    }
    __syncthreads();
    int ex = inc - s + wsum[wid];
    if (base     < NTOT) g_off[base]     = ex;
    if (base + 1 < NTOT) g_off[base + 1] = ex + v0;
    if (base + 2 < NTOT) g_off[base + 2] = ex + v0 + v1;
    if (base + 3 < NTOT) g_off[base + 3] = ex + v0 + v1 + v2;
}

// phase 2: scan the 137 block sums
__global__ void scan2_kernel() {
    __shared__ int sh[256];
    int t = threadIdx.x;
    int v = (t < NBLK) ? g_bsum[t] : 0;
    sh[t] = v;
    __syncthreads();
    for (int o = 1; o < 256; o <<= 1) {
        int n = (t >= o) ? sh[t - o] : 0;
        __syncthreads();
        sh[t] += n;
        __syncthreads();
    }
    if (t < NBLK) g_boff[t] = sh[t] - v;
    if (t == 255) g_off[NTOT] = sh[255];
}

// phase 3: add block offsets, init cursors + dinv
__global__ void scan3_kernel() {
    int i = blockIdx.x * blockDim.x + threadIdx.x;
    if (i >= NTOT) return;
    int off = g_off[i] + g_boff[i >> 10];
    g_off[i] = off;
    g_cur[i] = off;
    int d = g_deg[i];
    g_dinv[i] = (d > 0) ? rsqrtf((float)d) : 0.f;
}

// scatter edges into CSR, int4-vectorized
__global__ void build_adj_kernel(const int* __restrict__ up,
                                 const int* __restrict__ ut,
                                 const int* __restrict__ ug) {
    const int Q = EE / 4;
    int i = blockIdx.x * blockDim.x + threadIdx.x;
    if (i < Q) {
        int4 s = reinterpret_cast<const int4*>(up)[i];
        int4 d = reinterpret_cast<const int4*>(up + EE)[i];
        g_adj[atomicAdd(&g_cur[d.x], 1)] = s.x;
        g_adj[atomicAdd(&g_cur[d.y], 1)] = s.y;
        g_adj[atomicAdd(&g_cur[d.z], 1)] = s.z;
        g_adj[atomicAdd(&g_cur[d.w], 1)] = s.w;
    } else if (i < 2 * Q) {
        int4 s = reinterpret_cast<const int4*>(ut)[i - Q];
        int4 d = reinterpret_cast<const int4*>(ut + EE)[i - Q];
        g_adj[atomicAdd(&g_cur[NP + d.x], 1)] = s.x;
        g_adj[atomicAdd(&g_cur[NP + d.y], 1)] = s.y;
        g_adj[atomicAdd(&g_cur[NP + d.z], 1)] = s.z;
        g_adj[atomicAdd(&g_cur[NP + d.w], 1)] = s.w;
    } else if (i < 3 * Q) {
        int4 s = reinterpret_cast<const int4*>(ug)[i - 2 * Q];
        int4 d = reinterpret_cast<const int4*>(ug + EE)[i - 2 * Q];
        g_adj[atomicAdd(&g_cur[NP + NT + d.x], 1)] = s.x;
        g_adj[atomicAdd(&g_cur[NP + NT + d.y], 1)] = s.y;
        g_adj[atomicAdd(&g_cur[NP + NT + d.z], 1)] = s.z;
        g_adj[atomicAdd(&g_cur[NP + NT + d.w], 1)] = s.w;
    }
}

// ---------------------------------------------------------------
// warp-per-node conv, float4 lanes: half-warp h processes adjacency entries
// beg+h, beg+h+2, ... ; lane sub (0-15) owns dims 4*sub..4*sub+3.
__device__ __forceinline__ void conv_body(const float* __restrict__ tab,
                                          int base, int n, int o, int half,
                                          float4& acc) {
    int beg = g_off[n], end = g_off[n + 1];
    int k = beg + half;
    // 2-way unroll over this half's entries (stride 2)
    for (; k + 2 < end; k += 4) {
        int s0 = g_adj[k], s1 = g_adj[k + 2];
        float w0 = g_dinv[base + s0], w1 = g_dinv[base + s1];
        float4 v0 = *reinterpret_cast<const float4*>(tab + (size_t)s0 * DD + o);
        float4 v1 = *reinterpret_cast<const float4*>(tab + (size_t)s1 * DD + o);
        acc.x += w0 * v0.x + w1 * v1.x;
        acc.y += w0 * v0.y + w1 * v1.y;
        acc.z += w0 * v0.z + w1 * v1.z;
        acc.w += w0 * v0.w + w1 * v1.w;
    }
    if (k < end) {
        int s = g_adj[k];
        float w = g_dinv[base + s];
        float4 v = *reinterpret_cast<const float4*>(tab + (size_t)s * DD + o);
        acc.x += w * v.x; acc.y += w * v.y;
        acc.z += w * v.z; acc.w += w * v.w;
    }
}

__global__ void __launch_bounds__(256)
conv1_kernel(const float* __restrict__ e0, const float* __restrict__ e1,
             const float* __restrict__ e2) {
    int n = (blockIdx.x * blockDim.x + threadIdx.x) >> 5;
    if (n >= NTOT) return;
    int lane = threadIdx.x & 31;
    int half = lane >> 4, sub = lane & 15;
    int o = sub << 2;

    const float* tab;
    int base;
    if (n < NP)            { tab = e0; base = 0; }
    else if (n < NP + NT)  { tab = e1; base = NP; }
    else                   { tab = e2; base = NP + NT; }

    float4 acc = make_float4(0.f, 0.f, 0.f, 0.f);
    conv_body(tab, base, n, o, half, acc);

    // combine the two halves (sub-lane pairs hold same dims)
    acc.x += __shfl_xor_sync(0xffffffffu, acc.x, 16);
    acc.y += __shfl_xor_sync(0xffffffffu, acc.y, 16);
    acc.z += __shfl_xor_sync(0xffffffffu, acc.z, 16);
    acc.w += __shfl_xor_sync(0xffffffffu, acc.w, 16);

    if (half == 0) {
        float wd = g_dinv[n];
        *reinterpret_cast<float4*>(g_x1 + (size_t)n * DD + o) =
            make_float4(acc.x * wd, acc.y * wd, acc.z * wd, acc.w * wd);
    }
}

// Layer 2 + fused finalize: p = (emb + x1 + x2)/3 -> g_x2
__global__ void __launch_bounds__(256)
conv2_kernel(const float* __restrict__ e0, const float* __restrict__ e1,
             const float* __restrict__ e2) {
    int n = (blockIdx.x * blockDim.x + threadIdx.x) >> 5;
    if (n >= NTOT) return;
    int lane = threadIdx.x & 31;
    int half = lane >> 4, sub = lane & 15;
    int o = sub << 2;

    const float* emb;
    int base;
    if (n < NP)            { emb = e0; base = 0; }
    else if (n < NP + NT)  { emb = e1; base = NP; }
    else                   { emb = e2; base = NP + NT; }
    const float* tab = g_x1 + (size_t)base * DD;

    float4 acc = make_float4(0.f, 0.f, 0.f, 0.f);
    conv_body(tab, base, n - base + base, o, half, acc);  // n is global already

    acc.x += __shfl_xor_sync(0xffffffffu, acc.x, 16);
    acc.y += __shfl_xor_sync(0xffffffffu, acc.y, 16);
    acc.z += __shfl_xor_sync(0xffffffffu, acc.z, 16);
    acc.w += __shfl_xor_sync(0xffffffffu, acc.w, 16);

    if (half == 0) {
        float wd = g_dinv[n];
        size_t idx = (size_t)n * DD + o;
        float4 ev  = *reinterpret_cast<const float4*>(emb + (size_t)(n - base) * DD + o);
        float4 x1v = *reinterpret_cast<const float4*>(g_x1 + idx);
        const float k3 = 1.f / 3.f;
        *reinterpret_cast<float4*>(g_x2 + idx) =
            make_float4((ev.x + x1v.x + acc.x * wd) * k3,
                        (ev.y + x1v.y + acc.y * wd) * k3,
                        (ev.z + x1v.z + acc.z * wd) * k3,
                        (ev.w + x1v.w + acc.w * wd) * k3);
    }
}

// NOTE: conv_body uses g_off[n] with global n; adjacency entries are local ids.

// final fused per-edge kernel, float4 halves: half0 = src endpoint, half1 = dst.
__global__ void __launch_bounds__(256)
final_kernel(const int* __restrict__ up, const int* __restrict__ ut,
             const int* __restrict__ ug,
             const float* __restrict__ sfeat, const float* __restrict__ dfeat,
             const float* __restrict__ Ws, const float* __restrict__ bs,
             const float* __restrict__ Wd, const float* __restrict__ bd,
             float* __restrict__ out) {
    __shared__ float sWs[16 * 64];
    __shared__ float sWd[16 * 64];
    __shared__ float sbs[64];
    __shared__ float sbd[64];
    int t = threadIdx.x;
    for (int i = t; i < 1024; i += blockDim.x) { sWs[i] = Ws[i]; sWd[i] = Wd[i]; }
    if (t < 64) { sbs[t] = bs[t]; sbd[t] = bd[t]; }
    __syncthreads();

    int e = (blockIdx.x * blockDim.x + t) >> 5;
    if (e >= EE) return;
    int lane = t & 31;
    int half = lane >> 4, sub = lane & 15;
    int o = sub << 2;

    // feature linear for this endpoint (src for half0, dst for half1)
    const float* feat = half ? dfeat : sfeat;
    const float* W    = half ? sWd : sWs;
    const float* bb   = half ? sbd : sbs;
    float fv = feat[e * 16 + sub];
    float4 f = *reinterpret_cast<const float4*>(bb + o);
#pragma unroll
    for (int k = 0; k < 16; k++) {
        float a = __shfl_sync(0xffffffffu, fv, (half << 4) | k);
        float4 w = *reinterpret_cast<const float4*>(W + k * 64 + o);
        f.x = fmaf(a, w.x, f.x); f.y = fmaf(a, w.y, f.y);
        f.z = fmaf(a, w.z, f.z); f.w = fmaf(a, w.w, f.w);
    }

    // gathers: this half's endpoint index in each graph
    int i0 = up[e + half * EE];
    int i1 = ut[e + half * EE];
    int i2 = ug[e + half * EE];
    const float* P = g_x2;
    const float* T = g_x2 + (size_t)NP * DD;
    const float* G = g_x2 + (size_t)(NP + NT) * DD;
    float4 pv = *reinterpret_cast<const float4*>(P + (size_t)i0 * DD + o);
    float4 tv = *reinterpret_cast<const float4*>(T + (size_t)i1 * DD + o);
    float4 gv = *reinterpret_cast<const float4*>(G + (size_t)i2 * DD + o);

    const float k3 = 1.f / 3.f;
    float4 me;
    me.x = (pv.x + tv.x + gv.x) * k3 + f.x;
    me.y = (pv.y + tv.y + gv.y) * k3 + f.y;
    me.z = (pv.z + tv.z + gv.z) * k3 + f.z;
    me.w = (pv.w + tv.w + gv.w) * k3 + f.w;

    // exchange with the opposite endpoint's half
    float4 ot;
    ot.x = __shfl_xor_sync(0xffffffffu, me.x, 16);
    ot.y = __shfl_xor_sync(0xffffffffu, me.y, 16);
    ot.z = __shfl_xor_sync(0xffffffffu, me.z, 16);
    ot.w = __shfl_xor_sync(0xffffffffu, me.w, 16);

    float partial = me.x * ot.x + me.y * ot.y + me.z * ot.z + me.w * ot.w;
#pragma unroll
    for (int off = 8; off; off >>= 1)
        partial += __shfl_xor_sync(0xffffffffu, partial, off);
    // lanes 0 and 16 hold the full dot (identical); lane 0 writes
    if (lane == 0) out[e] = partial;
}

// ---------------------------------------------------------------
extern "C" void kernel_launch(void* const* d_in, const int* in_sizes, int n_in,
                              void* d_out, int out_size) {
    const int*   up     = (const int*)d_in[0];
    const int*   ut     = (const int*)d_in[1];
    const int*   ug     = (const int*)d_in[2];
    const float* sfeat  = (const float*)d_in[3];
    const float* dfeat  = (const float*)d_in[4];
    const float* up_emb = (const float*)d_in[5];
    const float* ut_emb = (const float*)d_in[6];
    const float* ug_emb = (const float*)d_in[7];
    const float* W_src  = (const float*)d_in[8];
    const float* b_src  = (const float*)d_in[9];
    const float* W_dst  = (const float*)d_in[10];
    const float* b_dst  = (const float*)d_in[11];
    float* out = (float*)d_out;

    void* degPtr = nullptr;
    cudaGetSymbolAddress(&degPtr, g_deg);
    cudaMemsetAsync(degPtr, 0, NTOT * sizeof(int));

    degree_kernel<<<(3 * (EE / 4) + 255) / 256, 256>>>(up, ut, ug);
    scan1_kernel<<<NBLK, 256>>>();
    scan2_kernel<<<1, 256>>>();
    scan3_kernel<<<(NTOT + 255) / 256, 256>>>();
    build_adj_kernel<<<(3 * (EE / 4) + 255) / 256, 256>>>(up, ut, ug);

    const int convGrid = (NTOT * 32 + 255) / 256;
    conv1_kernel<<<convGrid, 256>>>(up_emb, ut_emb, ug_emb);
    conv2_kernel<<<convGrid, 256>>>(up_emb, ut_emb, ug_emb);

    final_kernel<<<(EE * 32 + 255) / 256, 256>>>(up, ut, ug, sfeat, dfeat,
                                                 W_src, b_src, W_dst, b_dst, out);
}

// round 5
// speedup vs baseline: 1.9069x; 1.0948x over previous
#include <cuda_runtime.h>
#include <cuda_fp16.h>

#define NP 110000
#define NT 20000
#define NG 10000
#define NTOT (NP + NT + NG)   // 140000
#define EE 500000
#define DD 64

#define SCAN_CHUNK 1024
#define NBLK ((NTOT + SCAN_CHUNK - 1) / SCAN_CHUNK)   // 137

// ---- scratch (static device memory; no allocations allowed) ----
__device__ int   g_deg[NTOT];
__device__ int   g_off[NTOT + 1];
__device__ int   g_cur[NTOT];
__device__ int   g_bsum[NBLK];
__device__ int   g_boff[NBLK];
__device__ int   g_adj[3 * EE];
__device__ float g_dinv[NTOT];
__device__ __align__(16) __half g_embh[(size_t)NTOT * DD];  // fp16 copy of embeddings
__device__ __align__(16) __half g_x1h[(size_t)NTOT * DD];   // layer-1 output (fp16)
__device__ __align__(16) __half g_x2h[(size_t)NTOT * DD];   // final table p (fp16)

// ---------------------------------------------------------------
// convert fp32 embedding tables to fp16 (8 elems per thread)
__global__ void convert_kernel(const float* __restrict__ e0,
                               const float* __restrict__ e1,
                               const float* __restrict__ e2) {
    const int n0 = NP * DD / 8, n1 = NT * DD / 8, n2 = NG * DD / 8;
    int i = blockIdx.x * blockDim.x + threadIdx.x;
    const float4* src; __half* dst; int j;
    if (i < n0)                { src = (const float4*)e0; dst = g_embh;                         j = i; }
    else if (i < n0 + n1)      { src = (const float4*)e1; dst = g_embh + (size_t)NP * DD;       j = i - n0; }
    else if (i < n0 + n1 + n2) { src = (const float4*)e2; dst = g_embh + (size_t)(NP + NT) * DD; j = i - n0 - n1; }
    else return;
    float4 a = src[(size_t)j * 2], b = src[(size_t)j * 2 + 1];
    __half2 h0 = __floats2half2_rn(a.x, a.y), h1 = __floats2half2_rn(a.z, a.w);
    __half2 h2 = __floats2half2_rn(b.x, b.y), h3 = __floats2half2_rn(b.z, b.w);
    uint4 u;
    u.x = *reinterpret_cast<unsigned*>(&h0);
    u.y = *reinterpret_cast<unsigned*>(&h1);
    u.z = *reinterpret_cast<unsigned*>(&h2);
    u.w = *reinterpret_cast<unsigned*>(&h3);
    *reinterpret_cast<uint4*>(dst + (size_t)j * 8) = u;
}

// in-degree histogram, int4-vectorized (4 edges per thread)
__global__ void degree_kernel(const int* __restrict__ up,
                              const int* __restrict__ ut,
                              const int* __restrict__ ug) {
    const int Q = EE / 4;
    int i = blockIdx.x * blockDim.x + threadIdx.x;
    if (i < Q) {
        int4 d = reinterpret_cast<const int4*>(up + EE)[i];
        atomicAdd(&g_deg[d.x], 1); atomicAdd(&g_deg[d.y], 1);
        atomicAdd(&g_deg[d.z], 1); atomicAdd(&g_deg[d.w], 1);
    } else if (i < 2 * Q) {
        int4 d = reinterpret_cast<const int4*>(ut + EE)[i - Q];
        atomicAdd(&g_deg[NP + d.x], 1); atomicAdd(&g_deg[NP + d.y], 1);
        atomicAdd(&g_deg[NP + d.z], 1); atomicAdd(&g_deg[NP + d.w], 1);
    } else if (i < 3 * Q) {
        int4 d = reinterpret_cast<const int4*>(ug + EE)[i - 2 * Q];
        atomicAdd(&g_deg[NP + NT + d.x], 1); atomicAdd(&g_deg[NP + NT + d.y], 1);
        atomicAdd(&g_deg[NP + NT + d.z], 1); atomicAdd(&g_deg[NP + NT + d.w], 1);
    }
}

// phase 1: per-block exclusive prescan
__global__ void scan1_kernel() {
    __shared__ int wsum[8];
    int blk = blockIdx.x;
    int t = threadIdx.x;
    int lane = t & 31, wid = t >> 5;
    int base = blk * SCAN_CHUNK + t * 4;

    int v0 = 0, v1 = 0, v2 = 0, v3 = 0;
    if (base + 3 < NTOT) {
        v0 = g_deg[base]; v1 = g_deg[base + 1];
        v2 = g_deg[base + 2]; v3 = g_deg[base + 3];
    } else {
        if (base     < NTOT) v0 = g_deg[base];
        if (base + 1 < NTOT) v1 = g_deg[base + 1];
        if (base + 2 < NTOT) v2 = g_deg[base + 2];
        if (base + 3 < NTOT) v3 = g_deg[base + 3];
    }
    int s = v0 + v1 + v2 + v3;
    int inc = s;
#pragma unroll
    for (int o = 1; o < 32; o <<= 1) {
        int n = __shfl_up_sync(0xffffffffu, inc, o);
        if (lane >= o) inc += n;
    }
    if (lane == 31) wsum[wid] = inc;
    __syncthreads();
    if (t == 0) {
        int run = 0;
#pragma unroll
        for (int w = 0; w < 8; w++) { int x = wsum[w]; wsum[w] = run; run += x; }
        g_bsum[blk] = run;
    }
    __syncthreads();
    int ex = inc - s + wsum[wid];
    if (base     < NTOT) g_off[base]     = ex;
    if (base + 1 < NTOT) g_off[base + 1] = ex + v0;
    if (base + 2 < NTOT) g_off[base + 2] = ex + v0 + v1;
    if (base + 3 < NTOT) g_off[base + 3] = ex + v0 + v1 + v2;
}

// phase 2: scan block sums
__global__ void scan2_kernel() {
    __shared__ int sh[256];
    int t = threadIdx.x;
    int v = (t < NBLK) ? g_bsum[t] : 0;
    sh[t] = v;
    __syncthreads();
    for (int o = 1; o < 256; o <<= 1) {
        int n = (t >= o) ? sh[t - o] : 0;
        __syncthreads();
        sh[t] += n;
        __syncthreads();
    }
    if (t < NBLK) g_boff[t] = sh[t] - v;
    if (t == 255) g_off[NTOT] = sh[255];
}

// phase 3: add block offsets, init cursors + dinv
__global__ void scan3_kernel() {
    int i = blockIdx.x * blockDim.x + threadIdx.x;
    if (i >= NTOT) return;
    int off = g_off[i] + g_boff[i >> 10];
    g_off[i] = off;
    g_cur[i] = off;
    int d = g_deg[i];
    g_dinv[i] = (d > 0) ? rsqrtf((float)d) : 0.f;
}

// scatter edges into CSR, int4-vectorized
__global__ void build_adj_kernel(const int* __restrict__ up,
                                 const int* __restrict__ ut,
                                 const int* __restrict__ ug) {
    const int Q = EE / 4;
    int i = blockIdx.x * blockDim.x + threadIdx.x;
    if (i < Q) {
        int4 s = reinterpret_cast<const int4*>(up)[i];
        int4 d = reinterpret_cast<const int4*>(up + EE)[i];
        g_adj[atomicAdd(&g_cur[d.x], 1)] = s.x;
        g_adj[atomicAdd(&g_cur[d.y], 1)] = s.y;
        g_adj[atomicAdd(&g_cur[d.z], 1)] = s.z;
        g_adj[atomicAdd(&g_cur[d.w], 1)] = s.w;
    } else if (i < 2 * Q) {
        int4 s = reinterpret_cast<const int4*>(ut)[i - Q];
        int4 d = reinterpret_cast<const int4*>(ut + EE)[i - Q];
        g_adj[atomicAdd(&g_cur[NP + d.x], 1)] = s.x;
        g_adj[atomicAdd(&g_cur[NP + d.y], 1)] = s.y;
        g_adj[atomicAdd(&g_cur[NP + d.z], 1)] = s.z;
        g_adj[atomicAdd(&g_cur[NP + d.w], 1)] = s.w;
    } else if (i < 3 * Q) {
        int4 s = reinterpret_cast<const int4*>(ug)[i - 2 * Q];
        int4 d = reinterpret_cast<const int4*>(ug + EE)[i - 2 * Q];
        g_adj[atomicAdd(&g_cur[NP + NT + d.x], 1)] = s.x;
        g_adj[atomicAdd(&g_cur[NP + NT + d.y], 1)] = s.y;
        g_adj[atomicAdd(&g_cur[NP + NT + d.z], 1)] = s.z;
        g_adj[atomicAdd(&g_cur[NP + NT + d.w], 1)] = s.w;
    }
}

// ---------------------------------------------------------------
// fp16 row gather helper: 4 halves (8B) at element offset o of row s
__device__ __forceinline__ float4 load_h4(const __half* __restrict__ tab,
                                          int s, int o) {
    uint2 r = *reinterpret_cast<const uint2*>(tab + (size_t)s * DD + o);
    __half2 a = *reinterpret_cast<__half2*>(&r.x);
    __half2 b = *reinterpret_cast<__half2*>(&r.y);
    float2 fa = __half22float2(a), fb = __half22float2(b);
    return make_float4(fa.x, fa.y, fb.x, fb.y);
}

__device__ __forceinline__ void store_h4(__half* __restrict__ dst,
                                         int n, int o, float4 v) {
    __half2 a = __floats2half2_rn(v.x, v.y);
    __half2 b = __floats2half2_rn(v.z, v.w);
    uint2 u;
    u.x = *reinterpret_cast<unsigned*>(&a);
    u.y = *reinterpret_cast<unsigned*>(&b);
    *reinterpret_cast<uint2*>(dst + (size_t)n * DD + o) = u;
}

// warp-per-node conv, half-warp hf processes entries beg+hf, beg+hf+2, ...;
// lane sub (0-15) owns dims 4*sub..4*sub+3 (8 bytes fp16).
__device__ __forceinline__ void conv_body(const __half* __restrict__ tab,
                                          int base, int n, int o, int hf,
                                          float4& acc) {
    int beg = g_off[n], end = g_off[n + 1];
    int k = beg + hf;
    for (; k + 2 < end; k += 4) {
        int s0 = g_adj[k], s1 = g_adj[k + 2];
        float w0 = g_dinv[base + s0], w1 = g_dinv[base + s1];
        float4 v0 = load_h4(tab, s0, o);
        float4 v1 = load_h4(tab, s1, o);
        acc.x += w0 * v0.x + w1 * v1.x;
        acc.y += w0 * v0.y + w1 * v1.y;
        acc.z += w0 * v0.z + w1 * v1.z;
        acc.w += w0 * v0.w + w1 * v1.w;
    }
    if (k < end) {
        int s = g_adj[k];
        float w = g_dinv[base + s];
        float4 v = load_h4(tab, s, o);
        acc.x += w * v.x; acc.y += w * v.y;
        acc.z += w * v.z; acc.w += w * v.w;
    }
}

__global__ void __launch_bounds__(256)
conv1_kernel() {
    int n = (blockIdx.x * blockDim.x + threadIdx.x) >> 5;
    if (n >= NTOT) return;
    int lane = threadIdx.x & 31;
    int hf = lane >> 4, sub = lane & 15;
    int o = sub << 2;

    int base = (n < NP) ? 0 : (n < NP + NT) ? NP : (NP + NT);
    const __half* tab = g_embh + (size_t)base * DD;

    float4 acc = make_float4(0.f, 0.f, 0.f, 0.f);
    conv_body(tab, base, n, o, hf, acc);

    acc.x += __shfl_xor_sync(0xffffffffu, acc.x, 16);
    acc.y += __shfl_xor_sync(0xffffffffu, acc.y, 16);
    acc.z += __shfl_xor_sync(0xffffffffu, acc.z, 16);
    acc.w += __shfl_xor_sync(0xffffffffu, acc.w, 16);

    if (hf == 0) {
        float wd = g_dinv[n];
        store_h4(g_x1h, n, o,
                 make_float4(acc.x * wd, acc.y * wd, acc.z * wd, acc.w * wd));
    }
}

// Layer 2 + fused finalize: p = (emb + x1 + x2)/3 -> g_x2h
__global__ void __launch_bounds__(256)
conv2_kernel() {
    int n = (blockIdx.x * blockDim.x + threadIdx.x) >> 5;
    if (n >= NTOT) return;
    int lane = threadIdx.x & 31;
    int hf = lane >> 4, sub = lane & 15;
    int o = sub << 2;

    int base = (n < NP) ? 0 : (n < NP + NT) ? NP : (NP + NT);
    const __half* tab = g_x1h + (size_t)base * DD;

    float4 acc = make_float4(0.f, 0.f, 0.f, 0.f);
    conv_body(tab, base, n, o, hf, acc);

    acc.x += __shfl_xor_sync(0xffffffffu, acc.x, 16);
    acc.y += __shfl_xor_sync(0xffffffffu, acc.y, 16);
    acc.z += __shfl_xor_sync(0xffffffffu, acc.z, 16);
    acc.w += __shfl_xor_sync(0xffffffffu, acc.w, 16);

    if (hf == 0) {
        float wd = g_dinv[n];
        float4 ev  = load_h4(g_embh, n, o);
        float4 x1v = load_h4(g_x1h, n, o);
        const float k3 = 1.f / 3.f;
        store_h4(g_x2h, n, o,
                 make_float4((ev.x + x1v.x + acc.x * wd) * k3,
                             (ev.y + x1v.y + acc.y * wd) * k3,
                             (ev.z + x1v.z + acc.z * wd) * k3,
                             (ev.w + x1v.w + acc.w * wd) * k3));
    }
}

// final fused per-edge kernel: half0 = src endpoint, half1 = dst endpoint.
__global__ void __launch_bounds__(256)
final_kernel(const int* __restrict__ up, const int* __restrict__ ut,
             const int* __restrict__ ug,
             const float* __restrict__ sfeat, const float* __restrict__ dfeat,
             const float* __restrict__ Ws, const float* __restrict__ bs,
             const float* __restrict__ Wd, const float* __restrict__ bd,
             float* __restrict__ out) {
    __shared__ float sWs[16 * 64];
    __shared__ float sWd[16 * 64];
    __shared__ float sbs[64];
    __shared__ float sbd[64];
    int t = threadIdx.x;
    for (int i = t; i < 1024; i += blockDim.x) { sWs[i] = Ws[i]; sWd[i] = Wd[i]; }
    if (t < 64) { sbs[t] = bs[t]; sbd[t] = bd[t]; }
    __syncthreads();

    int e = (blockIdx.x * blockDim.x + t) >> 5;
    if (e >= EE) return;
    int lane = t & 31;
    int hf = lane >> 4, sub = lane & 15;
    int o = sub << 2;

    const float* feat = hf ? dfeat : sfeat;
    const float* W    = hf ? sWd : sWs;
    const float* bb   = hf ? sbd : sbs;
    float fv = feat[e * 16 + sub];
    float4 f = *reinterpret_cast<const float4*>(bb + o);
#pragma unroll
    for (int k = 0; k < 16; k++) {
        float a = __shfl_sync(0xffffffffu, fv, (hf << 4) | k);
        float4 w = *reinterpret_cast<const float4*>(W + k * 64 + o);
        f.x = fmaf(a, w.x, f.x); f.y = fmaf(a, w.y, f.y);
        f.z = fmaf(a, w.z, f.z); f.w = fmaf(a, w.w, f.w);
    }

    int i0 = up[e + hf * EE];
    int i1 = ut[e + hf * EE];
    int i2 = ug[e + hf * EE];
    const __half* P = g_x2h;
    const __half* T = g_x2h + (size_t)NP * DD;
    const __half* G = g_x2h + (size_t)(NP + NT) * DD;
    float4 pv = load_h4(P, i0, o);
    float4 tv = load_h4(T, i1, o);
    float4 gv = load_h4(G, i2, o);

    const float k3 = 1.f / 3.f;
    float4 me;
    me.x = (pv.x + tv.x + gv.x) * k3 + f.x;
    me.y = (pv.y + tv.y + gv.y) * k3 + f.y;
    me.z = (pv.z + tv.z + gv.z) * k3 + f.z;
    me.w = (pv.w + tv.w + gv.w) * k3 + f.w;

    float4 ot;
    ot.x = __shfl_xor_sync(0xffffffffu, me.x, 16);
    ot.y = __shfl_xor_sync(0xffffffffu, me.y, 16);
    ot.z = __shfl_xor_sync(0xffffffffu, me.z, 16);
    ot.w = __shfl_xor_sync(0xffffffffu, me.w, 16);

    float partial = me.x * ot.x + me.y * ot.y + me.z * ot.z + me.w * ot.w;
#pragma unroll
    for (int off = 8; off; off >>= 1)
        partial += __shfl_xor_sync(0xffffffffu, partial, off);
    if (lane == 0) out[e] = partial;
}

// ---------------------------------------------------------------
extern "C" void kernel_launch(void* const* d_in, const int* in_sizes, int n_in,
                              void* d_out, int out_size) {
    const int*   up     = (const int*)d_in[0];
    const int*   ut     = (const int*)d_in[1];
    const int*   ug     = (const int*)d_in[2];
    const float* sfeat  = (const float*)d_in[3];
    const float* dfeat  = (const float*)d_in[4];
    const float* up_emb = (const float*)d_in[5];
    const float* ut_emb = (const float*)d_in[6];
    const float* ug_emb = (const float*)d_in[7];
    const float* W_src  = (const float*)d_in[8];
    const float* b_src  = (const float*)d_in[9];
    const float* W_dst  = (const float*)d_in[10];
    const float* b_dst  = (const float*)d_in[11];
    float* out = (float*)d_out;

    void* degPtr = nullptr;
    cudaGetSymbolAddress(&degPtr, g_deg);
    cudaMemsetAsync(degPtr, 0, NTOT * sizeof(int));

    convert_kernel<<<(NTOT * DD / 8 + 255) / 256, 256>>>(up_emb, ut_emb, ug_emb);
    degree_kernel<<<(3 * (EE / 4) + 255) / 256, 256>>>(up, ut, ug);
    scan1_kernel<<<NBLK, 256>>>();
    scan2_kernel<<<1, 256>>>();
    scan3_kernel<<<(NTOT + 255) / 256, 256>>>();
    build_adj_kernel<<<(3 * (EE / 4) + 255) / 256, 256>>>(up, ut, ug);

    const int convGrid = (NTOT * 32 + 255) / 256;
    conv1_kernel<<<convGrid, 256>>>();
    conv2_kernel<<<convGrid, 256>>>();

    final_kernel<<<(EE * 32 + 255) / 256, 256>>>(up, ut, ug, sfeat, dfeat,
                                                 W_src, b_src, W_dst, b_dst, out);
}